// round 12
// baseline (speedup 1.0000x reference)
#include <cuda_runtime.h>
#include <cuda_bf16.h>
#include <math.h>
#include <float.h>
#include <stdint.h>

// tcgen05 only exists on the arch-specific (sm_103a) target. The bench also
// runs a family-generic compute_103 ptxas pass; that pass gets a stub body.
#if defined(__CUDA_ARCH__)
#  if defined(__CUDA_ARCH_FEAT_SM103_ALL)
#    define TC_OK 1
#  endif
#  ifndef TC_OK
#    ifdef __CUDA_ARCH_HAS_FEATURE__
#      if __CUDA_ARCH_HAS_FEATURE__(SM103_ALL)
#        define TC_OK 1
#      endif
#    endif
#  endif
#endif
#ifndef TC_OK
#  define TC_OK 0
#endif

#define NROWS 16384
#define DIM   64
#define NK    8192
#define TOPK  10
#define MTILE 128
#define NTILE 128
#define NTILES (NK / NTILE)   // 64

// out layout: quantized [0,1048576), total_loss @1048576, idx @1048577+row,
// min_d @1064961+row, perplexity @1081345
#define LOSS_OFF 1048576
#define IDX_OFF  1048577
#define MD_OFF   1064961
#define PERP_OFF 1081345

__device__ float g_counts[NK];
__device__ float g_nx[NROWS];
__device__ float g_ne[NK];
__device__ float g_loss;
__device__ float g_nvalid;

// ---------------- smem byte offsets (total kept at the R6-proven size) ------
#define SM_TMEM   0
#define SM_FULL0  16
#define SM_FULL1  24
#define SM_EMPTY0 32
#define SM_EMPTY1 40
#define SM_A      1024          // 3 splits x 16384 B (1024-aligned)
#define SM_B      50176         // 2 bufs x 3 splits x 16384 B (1024-aligned)
#define SM_TOTAL  148480

// kind::f16 idesc: dtype=F32, atype=btype=BF16, N=128, M=128  -> 0x8200490
#define IDESC ((1u<<4)|(1u<<7)|(1u<<10)|((NTILE/8)<<17)|((MTILE/16)<<24))
// SW128, version=1, SBO=64, LBO=1
#define DESC_BASE 0x4000404000010000ULL

__device__ __forceinline__ uint32_t smem_u32(const void* p) {
    uint32_t a;
    asm("{ .reg .u64 t; cvta.to.shared.u64 t, %1; cvt.u32.u64 %0, t; }"
        : "=r"(a) : "l"(p));
    return a;
}
__device__ __forceinline__ uint32_t sw128(uint32_t b) { return b ^ ((b >> 3) & 0x70); }

__device__ __forceinline__ void mbar_init(uint32_t a, uint32_t cnt) {
    asm volatile("mbarrier.init.shared.b64 [%0], %1;" :: "r"(a), "r"(cnt) : "memory");
}
__device__ __forceinline__ void mbar_arrive(uint32_t a) {
    asm volatile("mbarrier.arrive.shared.b64 _, [%0];" :: "r"(a) : "memory");
}
__device__ __forceinline__ void mbar_wait(uint32_t a, uint32_t parity) {
    asm volatile(
        "{\n\t.reg .pred P;\n"
        "WL_%=:\n\t"
        "mbarrier.try_wait.parity.acquire.cta.shared::cta.b64 P, [%0], %1, 0x989680;\n\t"
        "@P bra WD_%=;\n\t"
        "bra WL_%=;\n"
        "WD_%=:\n\t}"
        :: "r"(a), "r"(parity) : "memory");
}
__device__ __forceinline__ void fence_async_smem(){ asm volatile("fence.proxy.async.shared::cta;" ::: "memory"); }
__device__ __forceinline__ void bar_named(int id) {
    asm volatile("bar.sync %0, %1;" :: "r"(id), "r"(128) : "memory");
}

#if TC_OK
__device__ __forceinline__ void tc_commit(uint32_t mbar) {
    asm volatile("tcgen05.commit.cta_group::1.mbarrier::arrive::one.shared::cluster.b64 [%0];"
                 :: "r"(mbar) : "memory");
}
__device__ __forceinline__ void tc_fence_after()  { asm volatile("tcgen05.fence::after_thread_sync;"  ::: "memory"); }
__device__ __forceinline__ void tc_fence_before() { asm volatile("tcgen05.fence::before_thread_sync;" ::: "memory"); }
__device__ __forceinline__ void tc_wait_ld()      { asm volatile("tcgen05.wait::ld.sync.aligned;" ::: "memory"); }

__device__ __forceinline__ void mma_f16_ss(uint32_t d_tmem, uint64_t a_desc, uint64_t b_desc,
                                           uint32_t idesc, uint32_t enable) {
    asm volatile(
        "{\n\t.reg .pred p;\n\t"
        "setp.ne.u32 p, %4, 0;\n\t"
        "tcgen05.mma.cta_group::1.kind::f16 [%0], %1, %2, %3, {%5, %5, %5, %5}, p;\n\t}"
        :: "r"(d_tmem), "l"(a_desc), "l"(b_desc), "r"(idesc), "r"(enable), "r"(0u)
        : "memory");
}

#define LDTM_X32(r, addr) \
    asm volatile( \
        "tcgen05.ld.sync.aligned.32x32b.x32.b32 " \
        "{%0, %1, %2, %3, %4, %5, %6, %7, " \
        " %8, %9, %10, %11, %12, %13, %14, %15, " \
        " %16, %17, %18, %19, %20, %21, %22, %23, " \
        " %24, %25, %26, %27, %28, %29, %30, %31}, [%32];" \
        : "=r"((r)[0]),  "=r"((r)[1]),  "=r"((r)[2]),  "=r"((r)[3]), \
          "=r"((r)[4]),  "=r"((r)[5]),  "=r"((r)[6]),  "=r"((r)[7]), \
          "=r"((r)[8]),  "=r"((r)[9]),  "=r"((r)[10]), "=r"((r)[11]), \
          "=r"((r)[12]), "=r"((r)[13]), "=r"((r)[14]), "=r"((r)[15]), \
          "=r"((r)[16]), "=r"((r)[17]), "=r"((r)[18]), "=r"((r)[19]), \
          "=r"((r)[20]), "=r"((r)[21]), "=r"((r)[22]), "=r"((r)[23]), \
          "=r"((r)[24]), "=r"((r)[25]), "=r"((r)[26]), "=r"((r)[27]), \
          "=r"((r)[28]), "=r"((r)[29]), "=r"((r)[30]), "=r"((r)[31]) \
        : "r"(addr))
#endif  // TC_OK

__device__ __forceinline__ void split3(float x, uint16_t& h0, uint16_t& h1, uint16_t& h2) {
    __nv_bfloat16 b0 = __float2bfloat16_rn(x);
    float r = x - __bfloat162float(b0);
    __nv_bfloat16 b1 = __float2bfloat16_rn(r);
    r -= __bfloat162float(b1);
    __nv_bfloat16 b2 = __float2bfloat16_rn(r);
    h0 = __bfloat16_as_ushort(b0);
    h1 = __bfloat16_as_ushort(b1);
    h2 = __bfloat16_as_ushort(b2);
}

__device__ __forceinline__ bool lessdi(float a, int ai, float b, int bi) {
    return (a < b) || (a == b && ai < bi);
}

__device__ __forceinline__ void topk_insert(float dist, int ci,
                                            float (&td)[TOPK], int (&ti)[TOPK]) {
    if (lessdi(dist, ci, td[TOPK-1], ti[TOPK-1])) {
        #pragma unroll
        for (int s = TOPK-1; s >= 1; --s) {
            bool cm1 = lessdi(dist, ci, td[s-1], ti[s-1]);
            bool cs  = lessdi(dist, ci, td[s],   ti[s]);
            float nv = cm1 ? td[s-1] : dist;
            int  nvi = cm1 ? ti[s-1] : ci;
            if (cs) { td[s] = nv; ti[s] = nvi; }
        }
        if (lessdi(dist, ci, td[0], ti[0])) { td[0] = dist; ti[0] = ci; }
    }
}

// -------- prep: zero accumulators, compute exact fp32 norms --------
__global__ void vq_prep(const float* __restrict__ inp, const float* __restrict__ cb) {
    int tid = threadIdx.x, lane = tid & 31, w = tid >> 5;
    int gt = blockIdx.x * 256 + tid;
    if (gt < NK) g_counts[gt] = 0.f;
    if (gt == 0) { g_loss = 0.f; g_nvalid = 0.f; }
    int r = blockIdx.x * 8 + w;
    if (r < NROWS + NK) {
        const float* src = (r < NROWS) ? (inp + (size_t)r * DIM)
                                       : (cb + (size_t)(r - NROWS) * DIM);
        float2 v = ((const float2*)src)[lane];
        float s = v.x * v.x + v.y * v.y;
        #pragma unroll
        for (int o = 16; o > 0; o >>= 1) s += __shfl_xor_sync(0xffffffffu, s, o);
        if (lane == 0) {
            if (r < NROWS) g_nx[r] = s; else g_ne[r - NROWS] = s;
        }
    }
}

// -------- main: tcgen05 GEMM + fused top-k/sample/gather --------
__global__ void __launch_bounds__(256, 1)
vq_main(const float* __restrict__ inp, const float* __restrict__ cb,
        const float* __restrict__ gum, float* __restrict__ out)
{
#if TC_OK
    extern __shared__ char smem[];
    const uint32_t sb = smem_u32(smem);
    const int tid = threadIdx.x;
    const int lane = tid & 31;
    const int w = tid >> 5;
    const int row0 = blockIdx.x * MTILE;

    // TMEM alloc (warp 0), mbarrier init (tid 0)
    if (w == 0) {
        asm volatile("tcgen05.alloc.cta_group::1.sync.aligned.shared::cta.b32 [%0], %1;"
                     :: "r"(sb + SM_TMEM), "r"(256u) : "memory");
    }
    if (tid == 0) {
        mbar_init(sb + SM_FULL0, 1);  mbar_init(sb + SM_FULL1, 1);
        mbar_init(sb + SM_EMPTY0, 1); mbar_init(sb + SM_EMPTY1, 1);
    }

    // build A splits: 128 rows x 64 floats -> 3 bf16 tiles (SW128, 128 B/row)
    {
        const float4* src = (const float4*)(inp + (size_t)row0 * DIM);
        #pragma unroll
        for (int i = 0; i < 8; ++i) {
            int j = i * 256 + tid;           // j in [0,2048)
            int r4 = j >> 4, f4 = j & 15;
            float4 v = src[j];
            uint16_t x0,x1,x2, y0,y1,y2, z0,z1,z2, w0,w1,w2;
            split3(v.x, x0,x1,x2); split3(v.y, y0,y1,y2);
            split3(v.z, z0,z1,z2); split3(v.w, w0,w1,w2);
            uint32_t sw = sw128((uint32_t)(r4 * 128 + f4 * 8));
            *(uint2*)(smem + SM_A + sw) =
                make_uint2((uint32_t)x0 | ((uint32_t)y0 << 16), (uint32_t)z0 | ((uint32_t)w0 << 16));
            *(uint2*)(smem + SM_A + 16384 + sw) =
                make_uint2((uint32_t)x1 | ((uint32_t)y1 << 16), (uint32_t)z1 | ((uint32_t)w1 << 16));
            *(uint2*)(smem + SM_A + 32768 + sw) =
                make_uint2((uint32_t)x2 | ((uint32_t)y2 << 16), (uint32_t)z2 | ((uint32_t)w2 << 16));
        }
    }
    fence_async_smem();
    __syncthreads();
    uint32_t tmem_base;
    asm volatile("ld.shared.b32 %0, [%1];" : "=r"(tmem_base) : "r"(sb + SM_TMEM));

    if (tid >= 128) {
        // ================= producers + MMA (warps 4-7) =================
        const int pt = tid - 128;
        uint32_t pf[2] = {0u, 0u};   // wait full[] before B-smem reuse
        uint32_t pe[2] = {1u, 1u};   // wait empty[] before TMEM reuse (first pass free)
        const int SA[6] = {0, 0, 1, 1, 0, 2};
        const int SB[6] = {0, 1, 0, 1, 2, 0};

        for (int tile = 0; tile < NTILES; ++tile) {
            const int buf = tile & 1;
            const uint32_t full_b  = sb + SM_FULL0  + buf * 8;
            const uint32_t empty_b = sb + SM_EMPTY0 + buf * 8;
            if (tile >= 2) { mbar_wait(full_b, pf[buf]); pf[buf] ^= 1u; }

            const float4* src = (const float4*)(cb + (size_t)tile * NTILE * DIM);
            char* bbase = smem + SM_B + buf * 49152;
            #pragma unroll
            for (int i = 0; i < 16; ++i) {
                int j = i * 128 + pt;
                int r4 = j >> 4, f4 = j & 15;
                float4 v = src[j];
                uint16_t x0,x1,x2, y0,y1,y2, z0,z1,z2, w0,w1,w2;
                split3(v.x, x0,x1,x2); split3(v.y, y0,y1,y2);
                split3(v.z, z0,z1,z2); split3(v.w, w0,w1,w2);
                uint32_t sw = sw128((uint32_t)(r4 * 128 + f4 * 8));
                *(uint2*)(bbase + sw) =
                    make_uint2((uint32_t)x0 | ((uint32_t)y0 << 16), (uint32_t)z0 | ((uint32_t)w0 << 16));
                *(uint2*)(bbase + 16384 + sw) =
                    make_uint2((uint32_t)x1 | ((uint32_t)y1 << 16), (uint32_t)z1 | ((uint32_t)w1 << 16));
                *(uint2*)(bbase + 32768 + sw) =
                    make_uint2((uint32_t)x2 | ((uint32_t)y2 << 16), (uint32_t)z2 | ((uint32_t)w2 << 16));
            }
            fence_async_smem();
            bar_named(1);

            if (tid == 128) {
                mbar_wait(empty_b, pe[buf]); pe[buf] ^= 1u;
                tc_fence_after();
                const uint32_t d_tmem = tmem_base + buf * 128;
                #pragma unroll
                for (int t6 = 0; t6 < 6; ++t6) {
                    uint64_t ad = DESC_BASE | (((uint64_t)((sb + SM_A + SA[t6] * 16384) >> 4)) & 0x3FFF);
                    uint64_t bd = DESC_BASE | (((uint64_t)((sb + SM_B + buf * 49152 + SB[t6] * 16384) >> 4)) & 0x3FFF);
                    #pragma unroll
                    for (int k = 0; k < 4; ++k)
                        mma_f16_ss(d_tmem, ad + 2 * k, bd + 2 * k, IDESC,
                                   (t6 | k) ? 1u : 0u);
                }
                tc_commit(full_b);
            }
        }
    } else {
        // ================= epilogue (warps 0-3) =================
        uint32_t cf[2] = {0u, 0u};
        const int myrow = row0 + w * 32 + lane;
        const float nx = g_nx[myrow];
        float td[TOPK]; int ti[TOPK];
        #pragma unroll
        for (int i = 0; i < TOPK; ++i) { td[i] = FLT_MAX; ti[i] = 0x7fffffff; }

        for (int tile = 0; tile < NTILES; ++tile) {
            const int buf = tile & 1;
            const uint32_t full_b  = sb + SM_FULL0  + buf * 8;
            const uint32_t empty_b = sb + SM_EMPTY0 + buf * 8;
            mbar_wait(full_b, cf[buf]); cf[buf] ^= 1u;
            tc_fence_after();
            // ||e||^2 read straight from global (read-only, L2-resident 32KB)
            const float4* ne4 = (const float4*)(g_ne + tile * NTILE);
            #pragma unroll
            for (int g = 0; g < 4; ++g) {
                uint32_t r[32];
                LDTM_X32(r, tmem_base + buf * 128 + g * 32);
                tc_wait_ld();
                const int cb0 = tile * NTILE + g * 32;
                #pragma unroll
                for (int q = 0; q < 8; ++q) {
                    float4 ne = ne4[g * 8 + q];
                    float d0 = fmaf(__uint_as_float(r[q*4+0]), -2.f, nx + ne.x);
                    float d1 = fmaf(__uint_as_float(r[q*4+1]), -2.f, nx + ne.y);
                    float d2 = fmaf(__uint_as_float(r[q*4+2]), -2.f, nx + ne.z);
                    float d3 = fmaf(__uint_as_float(r[q*4+3]), -2.f, nx + ne.w);
                    topk_insert(d0, cb0 + q*4 + 0, td, ti);
                    topk_insert(d1, cb0 + q*4 + 1, td, ti);
                    topk_insert(d2, cb0 + q*4 + 2, td, ti);
                    topk_insert(d3, cb0 + q*4 + 3, td, ti);
                }
            }
            tc_fence_before();
            bar_named(2);
            if (tid == 0) mbar_arrive(empty_b);
        }

        // ---- gumbel sample over sorted top-10 (first-max tie like argmax) ----
        const unsigned FULL = 0xffffffffu;
        const float* g = gum + (size_t)myrow * TOPK;
        float y = g[0] - td[0]; int jj = 0;
        #pragma unroll
        for (int j = 1; j < TOPK; ++j) {
            float yj = g[j] - td[j];
            if (yj > y) { y = yj; jj = j; }
        }
        int   idx  = ti[jj];
        float mind = td[jj];
        bool valid = nx > 1e-12f;
        float vm = valid ? 1.f : 0.f;
        out[IDX_OFF + myrow] = valid ? (float)idx : 0.f;
        out[MD_OFF  + myrow] = valid ? mind : 0.f;
        atomicAdd(&g_counts[idx], vm);
        unsigned bal = __ballot_sync(FULL, valid);
        if (lane == 0) atomicAdd(&g_nvalid, (float)__popc(bal));

        // ---- cooperative quantized write + vq loss ----
        float lp = 0.f;
        #pragma unroll 4
        for (int r = 0; r < 32; ++r) {
            int   ridx = __shfl_sync(FULL, idx, r);
            float rvm  = __shfl_sync(FULL, vm,  r);
            int rr = row0 + w * 32 + r;
            float2 cv = ((const float2*)(cb  + (size_t)ridx * DIM))[lane];
            float2 xv = ((const float2*)(inp + (size_t)rr   * DIM))[lane];
            ((float2*)(out + (size_t)rr * DIM))[lane] = make_float2(cv.x * rvm, cv.y * rvm);
            float dx = cv.x - xv.x, dy = cv.y - xv.y;
            lp = fmaf(rvm * dx, dx, lp);
            lp = fmaf(rvm * dy, dy, lp);
        }
        #pragma unroll
        for (int o = 16; o > 0; o >>= 1) lp += __shfl_xor_sync(FULL, lp, o);
        if (lane == 0) atomicAdd(&g_loss, lp);
    }

    __syncthreads();
    if (w == 0) {
        asm volatile("tcgen05.relinquish_alloc_permit.cta_group::1.sync.aligned;");
        asm volatile("tcgen05.dealloc.cta_group::1.sync.aligned.b32 %0, %1;"
                     :: "r"(tmem_base), "r"(256u));
    }
#else
    // family-generic (compute_103) stub — never executed on GB300: the loader
    // picks the sm_103a SASS. Present only so this gencode pass compiles.
    if (blockIdx.x == 0 && threadIdx.x == 0) out[LOSS_OFF] = 0.f;
#endif
}

__global__ void vq_finalize(float* __restrict__ out) {
    __shared__ float red[256];
    int t = threadIdx.x;
    float nv = fmaxf(g_nvalid, 1.f);
    float h = 0.f;
    for (int i = t; i < NK; i += 256) {
        float p = g_counts[i] / nv;
        h += p * logf(p + 1e-10f);
    }
    red[t] = h; __syncthreads();
    for (int s = 128; s > 0; s >>= 1) { if (t < s) red[t] += red[t + s]; __syncthreads(); }
    if (t == 0) {
        float H = red[0];
        float perp = expf(-H);
        float ploss = -logf(perp + 1e-10f);
        float lvq = g_loss / (nv * (float)DIM);
        out[LOSS_OFF] = lvq + 0.01f * ploss;
        out[PERP_OFF] = perp;
    }
}

extern "C" void kernel_launch(void* const* d_in, const int* in_sizes, int n_in,
                              void* d_out, int out_size) {
    const float* inp = (const float*)d_in[0];
    const float* cbp = (const float*)d_in[1];
    const float* gum = (const float*)d_in[2];
    float* out = (float*)d_out;
    cudaFuncSetAttribute((const void*)vq_main,
                         cudaFuncAttributeMaxDynamicSharedMemorySize, SM_TOTAL);
    vq_prep<<<(NROWS + NK) / 8, 256>>>(inp, cbp);
    vq_main<<<NROWS / MTILE, 256, SM_TOTAL>>>(inp, cbp, gum, out);
    vq_finalize<<<1, 256>>>(out);
}

// round 13
// speedup vs baseline: 1.5564x; 1.5564x over previous
#include <cuda_runtime.h>
#include <cuda_bf16.h>
#include <math.h>
#include <float.h>
#include <stdint.h>
#include <cstdio>

// tcgen05 only exists on the arch-specific (sm_103a) target. The bench also
// runs a family-generic compute_103 ptxas pass; that pass gets a stub body.
#if defined(__CUDA_ARCH__)
#  if defined(__CUDA_ARCH_FEAT_SM103_ALL)
#    define TC_OK 1
#  endif
#  ifndef TC_OK
#    ifdef __CUDA_ARCH_HAS_FEATURE__
#      if __CUDA_ARCH_HAS_FEATURE__(SM103_ALL)
#        define TC_OK 1
#      endif
#    endif
#  endif
#endif
#ifndef TC_OK
#  define TC_OK 0
#endif

#define NROWS 16384
#define DIM   64
#define NK    8192
#define TOPK  10
#define MTILE 128
#define NTILE 128
#define NTILES (NK / NTILE)   // 64

// out layout: quantized [0,1048576), total_loss @1048576, idx @1048577+row,
// min_d @1064961+row, perplexity @1081345
#define LOSS_OFF 1048576
#define IDX_OFF  1048577
#define MD_OFF   1064961
#define PERP_OFF 1081345

__device__ float g_counts[NK];
__device__ float g_nx[NROWS];
__device__ float g_ne[NK];
__device__ float g_loss;
__device__ float g_nvalid;

// ---------------- smem byte offsets (R12-proven size) ----------------
#define SM_TMEM   0
#define SM_FULL0  16
#define SM_FULL1  24
#define SM_EMPTY0 32
#define SM_EMPTY1 40
#define SM_A      1024          // 3 splits x 16384 B (1024-aligned)
#define SM_B      50176         // 2 bufs x 3 splits x 16384 B (1024-aligned)
#define SM_TOTAL  148480

// kind::f16 idesc: dtype=F32, atype=btype=BF16, N=128, M=128  -> 0x8200490
#define IDESC ((1u<<4)|(1u<<7)|(1u<<10)|((NTILE/8)<<17)|((MTILE/16)<<24))
// SW128, version=1, SBO=64, LBO=1
#define DESC_BASE 0x4000404000010000ULL

__device__ __forceinline__ uint32_t smem_u32(const void* p) {
    uint32_t a;
    asm("{ .reg .u64 t; cvta.to.shared.u64 t, %1; cvt.u32.u64 %0, t; }"
        : "=r"(a) : "l"(p));
    return a;
}
__device__ __forceinline__ uint32_t sw128(uint32_t b) { return b ^ ((b >> 3) & 0x70); }

__device__ __forceinline__ void mbar_init(uint32_t a, uint32_t cnt) {
    asm volatile("mbarrier.init.shared.b64 [%0], %1;" :: "r"(a), "r"(cnt) : "memory");
}
__device__ __forceinline__ void mbar_arrive(uint32_t a) {
    asm volatile("mbarrier.arrive.shared.b64 _, [%0];" :: "r"(a) : "memory");
}
// POLLING wait (test_wait, no suspend) — the R13 experimental variable.
// try_wait's HW-sleep appeared to miss prompt wakeup on async-proxy
// (tcgen05.commit) arrives, costing a ~37us quantum per tile.
__device__ __forceinline__ void mbar_wait(uint32_t a, uint32_t parity) {
    asm volatile(
        "{\n\t.reg .pred P;\n"
        "WL_%=:\n\t"
        "mbarrier.test_wait.parity.acquire.cta.shared::cta.b64 P, [%0], %1;\n\t"
        "@!P bra WL_%=;\n\t}"
        :: "r"(a), "r"(parity) : "memory");
}
__device__ __forceinline__ void fence_async_smem(){ asm volatile("fence.proxy.async.shared::cta;" ::: "memory"); }
__device__ __forceinline__ void bar_named(int id) {
    asm volatile("bar.sync %0, %1;" :: "r"(id), "r"(128) : "memory");
}

#if TC_OK
__device__ __forceinline__ void tc_commit(uint32_t mbar) {
    asm volatile("tcgen05.commit.cta_group::1.mbarrier::arrive::one.shared::cluster.b64 [%0];"
                 :: "r"(mbar) : "memory");
}
__device__ __forceinline__ void tc_fence_after()  { asm volatile("tcgen05.fence::after_thread_sync;"  ::: "memory"); }
__device__ __forceinline__ void tc_fence_before() { asm volatile("tcgen05.fence::before_thread_sync;" ::: "memory"); }
__device__ __forceinline__ void tc_wait_ld()      { asm volatile("tcgen05.wait::ld.sync.aligned;" ::: "memory"); }

__device__ __forceinline__ void mma_f16_ss(uint32_t d_tmem, uint64_t a_desc, uint64_t b_desc,
                                           uint32_t idesc, uint32_t enable) {
    asm volatile(
        "{\n\t.reg .pred p;\n\t"
        "setp.ne.u32 p, %4, 0;\n\t"
        "tcgen05.mma.cta_group::1.kind::f16 [%0], %1, %2, %3, {%5, %5, %5, %5}, p;\n\t}"
        :: "r"(d_tmem), "l"(a_desc), "l"(b_desc), "r"(idesc), "r"(enable), "r"(0u)
        : "memory");
}

#define LDTM_X32(r, addr) \
    asm volatile( \
        "tcgen05.ld.sync.aligned.32x32b.x32.b32 " \
        "{%0, %1, %2, %3, %4, %5, %6, %7, " \
        " %8, %9, %10, %11, %12, %13, %14, %15, " \
        " %16, %17, %18, %19, %20, %21, %22, %23, " \
        " %24, %25, %26, %27, %28, %29, %30, %31}, [%32];" \
        : "=r"((r)[0]),  "=r"((r)[1]),  "=r"((r)[2]),  "=r"((r)[3]), \
          "=r"((r)[4]),  "=r"((r)[5]),  "=r"((r)[6]),  "=r"((r)[7]), \
          "=r"((r)[8]),  "=r"((r)[9]),  "=r"((r)[10]), "=r"((r)[11]), \
          "=r"((r)[12]), "=r"((r)[13]), "=r"((r)[14]), "=r"((r)[15]), \
          "=r"((r)[16]), "=r"((r)[17]), "=r"((r)[18]), "=r"((r)[19]), \
          "=r"((r)[20]), "=r"((r)[21]), "=r"((r)[22]), "=r"((r)[23]), \
          "=r"((r)[24]), "=r"((r)[25]), "=r"((r)[26]), "=r"((r)[27]), \
          "=r"((r)[28]), "=r"((r)[29]), "=r"((r)[30]), "=r"((r)[31]) \
        : "r"(addr))
#endif  // TC_OK

__device__ __forceinline__ void split3(float x, uint16_t& h0, uint16_t& h1, uint16_t& h2) {
    __nv_bfloat16 b0 = __float2bfloat16_rn(x);
    float r = x - __bfloat162float(b0);
    __nv_bfloat16 b1 = __float2bfloat16_rn(r);
    r -= __bfloat162float(b1);
    __nv_bfloat16 b2 = __float2bfloat16_rn(r);
    h0 = __bfloat16_as_ushort(b0);
    h1 = __bfloat16_as_ushort(b1);
    h2 = __bfloat16_as_ushort(b2);
}

__device__ __forceinline__ bool lessdi(float a, int ai, float b, int bi) {
    return (a < b) || (a == b && ai < bi);
}

__device__ __forceinline__ void topk_insert(float dist, int ci,
                                            float (&td)[TOPK], int (&ti)[TOPK]) {
    if (lessdi(dist, ci, td[TOPK-1], ti[TOPK-1])) {
        #pragma unroll
        for (int s = TOPK-1; s >= 1; --s) {
            bool cm1 = lessdi(dist, ci, td[s-1], ti[s-1]);
            bool cs  = lessdi(dist, ci, td[s],   ti[s]);
            float nv = cm1 ? td[s-1] : dist;
            int  nvi = cm1 ? ti[s-1] : ci;
            if (cs) { td[s] = nv; ti[s] = nvi; }
        }
        if (lessdi(dist, ci, td[0], ti[0])) { td[0] = dist; ti[0] = ci; }
    }
}

// -------- prep: zero accumulators, compute exact fp32 norms --------
__global__ void vq_prep(const float* __restrict__ inp, const float* __restrict__ cb) {
    int tid = threadIdx.x, lane = tid & 31, w = tid >> 5;
    int gt = blockIdx.x * 256 + tid;
    if (gt < NK) g_counts[gt] = 0.f;
    if (gt == 0) { g_loss = 0.f; g_nvalid = 0.f; }
    int r = blockIdx.x * 8 + w;
    if (r < NROWS + NK) {
        const float* src = (r < NROWS) ? (inp + (size_t)r * DIM)
                                       : (cb + (size_t)(r - NROWS) * DIM);
        float2 v = ((const float2*)src)[lane];
        float s = v.x * v.x + v.y * v.y;
        #pragma unroll
        for (int o = 16; o > 0; o >>= 1) s += __shfl_xor_sync(0xffffffffu, s, o);
        if (lane == 0) {
            if (r < NROWS) g_nx[r] = s; else g_ne[r - NROWS] = s;
        }
    }
}

// -------- main: tcgen05 GEMM + fused top-k/sample/gather --------
__global__ void __launch_bounds__(256, 1)
vq_main(const float* __restrict__ inp, const float* __restrict__ cb,
        const float* __restrict__ gum, float* __restrict__ out)
{
#if TC_OK
    extern __shared__ char smem[];
    const uint32_t sb = smem_u32(smem);
    const int tid = threadIdx.x;
    const int lane = tid & 31;
    const int w = tid >> 5;
    const int row0 = blockIdx.x * MTILE;

    // TMEM alloc (warp 0), mbarrier init (tid 0)
    if (w == 0) {
        asm volatile("tcgen05.alloc.cta_group::1.sync.aligned.shared::cta.b32 [%0], %1;"
                     :: "r"(sb + SM_TMEM), "r"(256u) : "memory");
    }
    if (tid == 0) {
        mbar_init(sb + SM_FULL0, 1);  mbar_init(sb + SM_FULL1, 1);
        mbar_init(sb + SM_EMPTY0, 1); mbar_init(sb + SM_EMPTY1, 1);
    }

    // build A splits: 128 rows x 64 floats -> 3 bf16 tiles (SW128, 128 B/row)
    {
        const float4* src = (const float4*)(inp + (size_t)row0 * DIM);
        #pragma unroll
        for (int i = 0; i < 8; ++i) {
            int j = i * 256 + tid;           // j in [0,2048)
            int r4 = j >> 4, f4 = j & 15;
            float4 v = src[j];
            uint16_t x0,x1,x2, y0,y1,y2, z0,z1,z2, w0,w1,w2;
            split3(v.x, x0,x1,x2); split3(v.y, y0,y1,y2);
            split3(v.z, z0,z1,z2); split3(v.w, w0,w1,w2);
            uint32_t sw = sw128((uint32_t)(r4 * 128 + f4 * 8));
            *(uint2*)(smem + SM_A + sw) =
                make_uint2((uint32_t)x0 | ((uint32_t)y0 << 16), (uint32_t)z0 | ((uint32_t)w0 << 16));
            *(uint2*)(smem + SM_A + 16384 + sw) =
                make_uint2((uint32_t)x1 | ((uint32_t)y1 << 16), (uint32_t)z1 | ((uint32_t)w1 << 16));
            *(uint2*)(smem + SM_A + 32768 + sw) =
                make_uint2((uint32_t)x2 | ((uint32_t)y2 << 16), (uint32_t)z2 | ((uint32_t)w2 << 16));
        }
    }
    fence_async_smem();
    __syncthreads();
    uint32_t tmem_base;
    asm volatile("ld.shared.b32 %0, [%1];" : "=r"(tmem_base) : "r"(sb + SM_TMEM));

    if (tid >= 128) {
        // ================= producers + MMA (warps 4-7) =================
        const int pt = tid - 128;
        uint32_t pf[2] = {0u, 0u};   // wait full[] before B-smem reuse
        uint32_t pe[2] = {1u, 1u};   // wait empty[] before TMEM reuse (first pass free)
        const int SA[6] = {0, 0, 1, 1, 0, 2};
        const int SB[6] = {0, 1, 0, 1, 2, 0};
        unsigned p_t0 = clock();
        unsigned p_wf = 0, p_we = 0;

        for (int tile = 0; tile < NTILES; ++tile) {
            const int buf = tile & 1;
            const uint32_t full_b  = sb + SM_FULL0  + buf * 8;
            const uint32_t empty_b = sb + SM_EMPTY0 + buf * 8;
            if (tile >= 2) {
                unsigned c0 = clock();
                mbar_wait(full_b, pf[buf]); pf[buf] ^= 1u;
                p_wf += clock() - c0;
            }

            const float4* src = (const float4*)(cb + (size_t)tile * NTILE * DIM);
            char* bbase = smem + SM_B + buf * 49152;
            #pragma unroll
            for (int i = 0; i < 16; ++i) {
                int j = i * 128 + pt;
                int r4 = j >> 4, f4 = j & 15;
                float4 v = src[j];
                uint16_t x0,x1,x2, y0,y1,y2, z0,z1,z2, w0,w1,w2;
                split3(v.x, x0,x1,x2); split3(v.y, y0,y1,y2);
                split3(v.z, z0,z1,z2); split3(v.w, w0,w1,w2);
                uint32_t sw = sw128((uint32_t)(r4 * 128 + f4 * 8));
                *(uint2*)(bbase + sw) =
                    make_uint2((uint32_t)x0 | ((uint32_t)y0 << 16), (uint32_t)z0 | ((uint32_t)w0 << 16));
                *(uint2*)(bbase + 16384 + sw) =
                    make_uint2((uint32_t)x1 | ((uint32_t)y1 << 16), (uint32_t)z1 | ((uint32_t)w1 << 16));
                *(uint2*)(bbase + 32768 + sw) =
                    make_uint2((uint32_t)x2 | ((uint32_t)y2 << 16), (uint32_t)z2 | ((uint32_t)w2 << 16));
            }
            fence_async_smem();
            bar_named(1);

            if (tid == 128) {
                unsigned c0 = clock();
                mbar_wait(empty_b, pe[buf]); pe[buf] ^= 1u;
                p_we += clock() - c0;
                tc_fence_after();
                const uint32_t d_tmem = tmem_base + buf * 128;
                #pragma unroll
                for (int t6 = 0; t6 < 6; ++t6) {
                    uint64_t ad = DESC_BASE | (((uint64_t)((sb + SM_A + SA[t6] * 16384) >> 4)) & 0x3FFF);
                    uint64_t bd = DESC_BASE | (((uint64_t)((sb + SM_B + buf * 49152 + SB[t6] * 16384) >> 4)) & 0x3FFF);
                    #pragma unroll
                    for (int k = 0; k < 4; ++k)
                        mma_f16_ss(d_tmem, ad + 2 * k, bd + 2 * k, IDESC,
                                   (t6 | k) ? 1u : 0u);
                }
                tc_commit(full_b);
            }
        }
        if (tid == 128 && blockIdx.x == 0)
            printf("PROD tot=%u wait_full=%u wait_empty=%u\n",
                   clock() - p_t0, p_wf, p_we);
    } else {
        // ================= epilogue (warps 0-3) =================
        uint32_t cf[2] = {0u, 0u};
        const int myrow = row0 + w * 32 + lane;
        const float nx = g_nx[myrow];
        float td[TOPK]; int ti[TOPK];
        #pragma unroll
        for (int i = 0; i < TOPK; ++i) { td[i] = FLT_MAX; ti[i] = 0x7fffffff; }
        unsigned e_t0 = clock();
        unsigned e_wf = 0;

        for (int tile = 0; tile < NTILES; ++tile) {
            const int buf = tile & 1;
            const uint32_t full_b  = sb + SM_FULL0  + buf * 8;
            const uint32_t empty_b = sb + SM_EMPTY0 + buf * 8;
            unsigned c0 = clock();
            mbar_wait(full_b, cf[buf]); cf[buf] ^= 1u;
            e_wf += clock() - c0;
            tc_fence_after();
            // ||e||^2 read straight from global (read-only, L2-resident 32KB)
            const float4* ne4 = (const float4*)(g_ne + tile * NTILE);
            #pragma unroll
            for (int g = 0; g < 4; ++g) {
                uint32_t r[32];
                LDTM_X32(r, tmem_base + buf * 128 + g * 32);
                tc_wait_ld();
                const int cb0 = tile * NTILE + g * 32;
                #pragma unroll
                for (int q = 0; q < 8; ++q) {
                    float4 ne = ne4[g * 8 + q];
                    float d0 = fmaf(__uint_as_float(r[q*4+0]), -2.f, nx + ne.x);
                    float d1 = fmaf(__uint_as_float(r[q*4+1]), -2.f, nx + ne.y);
                    float d2 = fmaf(__uint_as_float(r[q*4+2]), -2.f, nx + ne.z);
                    float d3 = fmaf(__uint_as_float(r[q*4+3]), -2.f, nx + ne.w);
                    topk_insert(d0, cb0 + q*4 + 0, td, ti);
                    topk_insert(d1, cb0 + q*4 + 1, td, ti);
                    topk_insert(d2, cb0 + q*4 + 2, td, ti);
                    topk_insert(d3, cb0 + q*4 + 3, td, ti);
                }
            }
            tc_fence_before();
            bar_named(2);
            if (tid == 0) mbar_arrive(empty_b);
        }
        if (tid == 0 && blockIdx.x == 0)
            printf("EPI  tot=%u wait_full=%u\n", clock() - e_t0, e_wf);

        // ---- gumbel sample over sorted top-10 (static-index select) ----
        const unsigned FULL = 0xffffffffu;
        const float* g = gum + (size_t)myrow * TOPK;
        float best = g[0] - td[0];
        int   idx  = ti[0];
        float mind = td[0];
        #pragma unroll
        for (int j = 1; j < TOPK; ++j) {
            float yj = g[j] - td[j];
            if (yj > best) { best = yj; idx = ti[j]; mind = td[j]; }
        }
        bool valid = nx > 1e-12f;
        float vm = valid ? 1.f : 0.f;
        out[IDX_OFF + myrow] = valid ? (float)idx : 0.f;
        out[MD_OFF  + myrow] = valid ? mind : 0.f;
        atomicAdd(&g_counts[idx], vm);
        unsigned bal = __ballot_sync(FULL, valid);
        if (lane == 0) atomicAdd(&g_nvalid, (float)__popc(bal));

        // ---- cooperative quantized write + vq loss ----
        float lp = 0.f;
        #pragma unroll 4
        for (int r = 0; r < 32; ++r) {
            int   ridx = __shfl_sync(FULL, idx, r);
            float rvm  = __shfl_sync(FULL, vm,  r);
            int rr = row0 + w * 32 + r;
            float2 cv = ((const float2*)(cb  + (size_t)ridx * DIM))[lane];
            float2 xv = ((const float2*)(inp + (size_t)rr   * DIM))[lane];
            ((float2*)(out + (size_t)rr * DIM))[lane] = make_float2(cv.x * rvm, cv.y * rvm);
            float dx = cv.x - xv.x, dy = cv.y - xv.y;
            lp = fmaf(rvm * dx, dx, lp);
            lp = fmaf(rvm * dy, dy, lp);
        }
        #pragma unroll
        for (int o = 16; o > 0; o >>= 1) lp += __shfl_xor_sync(FULL, lp, o);
        if (lane == 0) atomicAdd(&g_loss, lp);
    }

    __syncthreads();
    if (w == 0) {
        asm volatile("tcgen05.relinquish_alloc_permit.cta_group::1.sync.aligned;");
        asm volatile("tcgen05.dealloc.cta_group::1.sync.aligned.b32 %0, %1;"
                     :: "r"(tmem_base), "r"(256u));
    }
#else
    // family-generic (compute_103) stub — never executed on GB300: the loader
    // picks the sm_103a SASS. Present only so this gencode pass compiles.
    if (blockIdx.x == 0 && threadIdx.x == 0) out[LOSS_OFF] = 0.f;
#endif
}

__global__ void vq_finalize(float* __restrict__ out) {
    __shared__ float red[256];
    int t = threadIdx.x;
    float nv = fmaxf(g_nvalid, 1.f);
    float h = 0.f;
    for (int i = t; i < NK; i += 256) {
        float p = g_counts[i] / nv;
        h += p * logf(p + 1e-10f);
    }
    red[t] = h; __syncthreads();
    for (int s = 128; s > 0; s >>= 1) { if (t < s) red[t] += red[t + s]; __syncthreads(); }
    if (t == 0) {
        float H = red[0];
        float perp = expf(-H);
        float ploss = -logf(perp + 1e-10f);
        float lvq = g_loss / (nv * (float)DIM);
        out[LOSS_OFF] = lvq + 0.01f * ploss;
        out[PERP_OFF] = perp;
    }
}

extern "C" void kernel_launch(void* const* d_in, const int* in_sizes, int n_in,
                              void* d_out, int out_size) {
    const float* inp = (const float*)d_in[0];
    const float* cbp = (const float*)d_in[1];
    const float* gum = (const float*)d_in[2];
    float* out = (float*)d_out;
    cudaFuncSetAttribute((const void*)vq_main,
                         cudaFuncAttributeMaxDynamicSharedMemorySize, SM_TOTAL);
    vq_prep<<<(NROWS + NK) / 8, 256>>>(inp, cbp);
    vq_main<<<NROWS / MTILE, 256, SM_TOTAL>>>(inp, cbp, gum, out);
    vq_finalize<<<1, 256>>>(out);
}

// round 14
// speedup vs baseline: 4.1775x; 2.6841x over previous
#include <cuda_runtime.h>
#include <cuda_bf16.h>
#include <math.h>
#include <float.h>
#include <stdint.h>
#include <cstdio>

// tcgen05 only exists on the arch-specific (sm_103a) target. The bench also
// runs a family-generic compute_103 ptxas pass; that pass gets a stub body.
#if defined(__CUDA_ARCH__)
#  if defined(__CUDA_ARCH_FEAT_SM103_ALL)
#    define TC_OK 1
#  endif
#  ifndef TC_OK
#    ifdef __CUDA_ARCH_HAS_FEATURE__
#      if __CUDA_ARCH_HAS_FEATURE__(SM103_ALL)
#        define TC_OK 1
#      endif
#    endif
#  endif
#endif
#ifndef TC_OK
#  define TC_OK 0
#endif

#define NROWS 16384
#define DIM   64
#define NK    8192
#define TOPK  10
#define MTILE 128
#define NTILE 128
#define NTILES (NK / NTILE)   // 64

#define LOSS_OFF 1048576
#define IDX_OFF  1048577
#define MD_OFF   1064961
#define PERP_OFF 1081345

__device__ float g_counts[NK];
__device__ float g_nx[NROWS];
__device__ float g_ne[NK];
__device__ float g_loss;
__device__ float g_nvalid;

// ---------------- smem byte offsets (R12-proven total) ----------------
#define SM_TMEM   0
#define SM_FULL0  16
#define SM_FULL1  24
#define SM_A      1024          // 3 splits x 16384 B
#define SM_B      50176         // 2 bufs x 3 splits x 16384 B
#define SM_MERGE  SM_B          // reused after last MMA for top-k merge lists
#define SM_TOTAL  148480

// kind::f16 idesc: dtype=F32, atype=btype=BF16, N=128, M=128 -> 0x8200490
#define IDESC ((1u<<4)|(1u<<7)|(1u<<10)|((NTILE/8)<<17)|((MTILE/16)<<24))
// SW128, version=1, SBO=64, LBO=1
#define DESC_BASE 0x4000404000010000ULL

__device__ __forceinline__ uint32_t smem_u32(const void* p) {
    uint32_t a;
    asm("{ .reg .u64 t; cvta.to.shared.u64 t, %1; cvt.u32.u64 %0, t; }"
        : "=r"(a) : "l"(p));
    return a;
}
__device__ __forceinline__ uint32_t sw128(uint32_t b) { return b ^ ((b >> 3) & 0x70); }

__device__ __forceinline__ void mbar_init(uint32_t a, uint32_t cnt) {
    asm volatile("mbarrier.init.shared.b64 [%0], %1;" :: "r"(a), "r"(cnt) : "memory");
}
// polling wait (test_wait, no suspend) — proven faster than try_wait here (R13)
__device__ __forceinline__ void mbar_wait(uint32_t a, uint32_t parity) {
    asm volatile(
        "{\n\t.reg .pred P;\n"
        "WL_%=:\n\t"
        "mbarrier.test_wait.parity.acquire.cta.shared::cta.b64 P, [%0], %1;\n\t"
        "@!P bra WL_%=;\n\t}"
        :: "r"(a), "r"(parity) : "memory");
}
__device__ __forceinline__ void fence_async_smem(){ asm volatile("fence.proxy.async.shared::cta;" ::: "memory"); }

#if TC_OK
__device__ __forceinline__ void tc_commit(uint32_t mbar) {
    asm volatile("tcgen05.commit.cta_group::1.mbarrier::arrive::one.shared::cluster.b64 [%0];"
                 :: "r"(mbar) : "memory");
}
__device__ __forceinline__ void tc_fence_after()  { asm volatile("tcgen05.fence::after_thread_sync;"  ::: "memory"); }
__device__ __forceinline__ void tc_fence_before() { asm volatile("tcgen05.fence::before_thread_sync;" ::: "memory"); }
__device__ __forceinline__ void tc_wait_ld()      { asm volatile("tcgen05.wait::ld.sync.aligned;" ::: "memory"); }

__device__ __forceinline__ void mma_f16_ss(uint32_t d_tmem, uint64_t a_desc, uint64_t b_desc,
                                           uint32_t idesc, uint32_t enable) {
    asm volatile(
        "{\n\t.reg .pred p;\n\t"
        "setp.ne.u32 p, %4, 0;\n\t"
        "tcgen05.mma.cta_group::1.kind::f16 [%0], %1, %2, %3, {%5, %5, %5, %5}, p;\n\t}"
        :: "r"(d_tmem), "l"(a_desc), "l"(b_desc), "r"(idesc), "r"(enable), "r"(0u)
        : "memory");
}

#define LDTM_X32(r, addr) \
    asm volatile( \
        "tcgen05.ld.sync.aligned.32x32b.x32.b32 " \
        "{%0, %1, %2, %3, %4, %5, %6, %7, " \
        " %8, %9, %10, %11, %12, %13, %14, %15, " \
        " %16, %17, %18, %19, %20, %21, %22, %23, " \
        " %24, %25, %26, %27, %28, %29, %30, %31}, [%32];" \
        : "=r"((r)[0]),  "=r"((r)[1]),  "=r"((r)[2]),  "=r"((r)[3]), \
          "=r"((r)[4]),  "=r"((r)[5]),  "=r"((r)[6]),  "=r"((r)[7]), \
          "=r"((r)[8]),  "=r"((r)[9]),  "=r"((r)[10]), "=r"((r)[11]), \
          "=r"((r)[12]), "=r"((r)[13]), "=r"((r)[14]), "=r"((r)[15]), \
          "=r"((r)[16]), "=r"((r)[17]), "=r"((r)[18]), "=r"((r)[19]), \
          "=r"((r)[20]), "=r"((r)[21]), "=r"((r)[22]), "=r"((r)[23]), \
          "=r"((r)[24]), "=r"((r)[25]), "=r"((r)[26]), "=r"((r)[27]), \
          "=r"((r)[28]), "=r"((r)[29]), "=r"((r)[30]), "=r"((r)[31]) \
        : "r"(addr))
#endif  // TC_OK

__device__ __forceinline__ void split3(float x, uint16_t& h0, uint16_t& h1, uint16_t& h2) {
    __nv_bfloat16 b0 = __float2bfloat16_rn(x);
    float r = x - __bfloat162float(b0);
    __nv_bfloat16 b1 = __float2bfloat16_rn(r);
    r -= __bfloat162float(b1);
    __nv_bfloat16 b2 = __float2bfloat16_rn(r);
    h0 = __bfloat16_as_ushort(b0);
    h1 = __bfloat16_as_ushort(b1);
    h2 = __bfloat16_as_ushort(b2);
}

__device__ __forceinline__ bool lessdi(float a, int ai, float b, int bi) {
    return (a < b) || (a == b && ai < bi);
}

__device__ __forceinline__ void topk_insert(float dist, int ci,
                                            float (&td)[TOPK], int (&ti)[TOPK]) {
    if (lessdi(dist, ci, td[TOPK-1], ti[TOPK-1])) {
        #pragma unroll
        for (int s = TOPK-1; s >= 1; --s) {
            bool cm1 = lessdi(dist, ci, td[s-1], ti[s-1]);
            bool cs  = lessdi(dist, ci, td[s],   ti[s]);
            float nv = cm1 ? td[s-1] : dist;
            int  nvi = cm1 ? ti[s-1] : ci;
            if (cs) { td[s] = nv; ti[s] = nvi; }
        }
        if (lessdi(dist, ci, td[0], ti[0])) { td[0] = dist; ti[0] = ci; }
    }
}

// -------- prep: zero accumulators, compute exact fp32 norms --------
__global__ void vq_prep(const float* __restrict__ inp, const float* __restrict__ cb) {
    int tid = threadIdx.x, lane = tid & 31, w = tid >> 5;
    int gt = blockIdx.x * 256 + tid;
    if (gt < NK) g_counts[gt] = 0.f;
    if (gt == 0) { g_loss = 0.f; g_nvalid = 0.f; }
    int r = blockIdx.x * 8 + w;
    if (r < NROWS + NK) {
        const float* src = (r < NROWS) ? (inp + (size_t)r * DIM)
                                       : (cb + (size_t)(r - NROWS) * DIM);
        float2 v = ((const float2*)src)[lane];
        float s = v.x * v.x + v.y * v.y;
        #pragma unroll
        for (int o = 16; o > 0; o >>= 1) s += __shfl_xor_sync(0xffffffffu, s, o);
        if (lane == 0) {
            if (r < NROWS) g_nx[r] = s; else g_ne[r - NROWS] = s;
        }
    }
}

// -------- main: bulk-sync pipelined tcgen05 GEMM + fused top-k --------
__global__ void __launch_bounds__(256, 1)
vq_main(const float* __restrict__ inp, const float* __restrict__ cb,
        const float* __restrict__ gum, float* __restrict__ out)
{
#if TC_OK
    extern __shared__ char smem[];
    const uint32_t sb = smem_u32(smem);
    const int tid = threadIdx.x;
    const int lane = tid & 31;
    const int w = tid >> 5;
    const int h = w >> 2;          // column half: warps 0-3 -> cols 0-63, 4-7 -> 64-127
    const int sp = w & 3;          // TMEM subpartition (rows sp*32..sp*32+31)
    const int row0 = blockIdx.x * MTILE;

    if (w == 0) {
        asm volatile("tcgen05.alloc.cta_group::1.sync.aligned.shared::cta.b32 [%0], %1;"
                     :: "r"(sb + SM_TMEM), "r"(256u) : "memory");
    }
    if (tid == 0) { mbar_init(sb + SM_FULL0, 1); mbar_init(sb + SM_FULL1, 1); }

    // build A splits: 128 rows x 64 floats -> 3 bf16 tiles (SW128, 128 B/row)
    {
        const float4* src = (const float4*)(inp + (size_t)row0 * DIM);
        #pragma unroll
        for (int i = 0; i < 8; ++i) {
            int j = i * 256 + tid;
            int r4 = j >> 4, f4 = j & 15;
            float4 v = src[j];
            uint16_t x0,x1,x2, y0,y1,y2, z0,z1,z2, w0,w1,w2;
            split3(v.x, x0,x1,x2); split3(v.y, y0,y1,y2);
            split3(v.z, z0,z1,z2); split3(v.w, w0,w1,w2);
            uint32_t sw = sw128((uint32_t)(r4 * 128 + f4 * 8));
            *(uint2*)(smem + SM_A + sw) =
                make_uint2((uint32_t)x0 | ((uint32_t)y0 << 16), (uint32_t)z0 | ((uint32_t)w0 << 16));
            *(uint2*)(smem + SM_A + 16384 + sw) =
                make_uint2((uint32_t)x1 | ((uint32_t)y1 << 16), (uint32_t)z1 | ((uint32_t)w1 << 16));
            *(uint2*)(smem + SM_A + 32768 + sw) =
                make_uint2((uint32_t)x2 | ((uint32_t)y2 << 16), (uint32_t)z2 | ((uint32_t)w2 << 16));
        }
    }
    fence_async_smem();
    __syncthreads();
    uint32_t tmem_base;
    asm volatile("ld.shared.b32 %0, [%1];" : "=r"(tmem_base) : "r"(sb + SM_TMEM));

    const int myrow = row0 + sp * 32 + lane;
    const float nx = g_nx[myrow];
    float td[TOPK]; int ti[TOPK];
    #pragma unroll
    for (int i = 0; i < TOPK; ++i) { td[i] = FLT_MAX; ti[i] = 0x7fffffff; }

    uint32_t cf[2] = {0u, 0u};
    const int SA[6] = {0, 0, 1, 1, 0, 2};
    const int SB[6] = {0, 1, 0, 1, 2, 0};
    unsigned t0 = clock();
    unsigned c_wait = 0, c_conv = 0;

    for (int tile = 0; tile <= NTILES; ++tile) {
        // ---- phase 1: convert B(tile) + issue MMA(tile) ----
        if (tile < NTILES) {
            const int buf = tile & 1;
            unsigned cc0 = clock();
            const float4* src = (const float4*)(cb + (size_t)tile * NTILE * DIM);
            char* bbase = smem + SM_B + buf * 49152;
            #pragma unroll
            for (int i = 0; i < 8; ++i) {
                int j = i * 256 + tid;
                int r4 = j >> 4, f4 = j & 15;
                float4 v = src[j];
                uint16_t x0,x1,x2, y0,y1,y2, z0,z1,z2, w0,w1,w2;
                split3(v.x, x0,x1,x2); split3(v.y, y0,y1,y2);
                split3(v.z, z0,z1,z2); split3(v.w, w0,w1,w2);
                uint32_t sw = sw128((uint32_t)(r4 * 128 + f4 * 8));
                *(uint2*)(bbase + sw) =
                    make_uint2((uint32_t)x0 | ((uint32_t)y0 << 16), (uint32_t)z0 | ((uint32_t)w0 << 16));
                *(uint2*)(bbase + 16384 + sw) =
                    make_uint2((uint32_t)x1 | ((uint32_t)y1 << 16), (uint32_t)z1 | ((uint32_t)w1 << 16));
                *(uint2*)(bbase + 32768 + sw) =
                    make_uint2((uint32_t)x2 | ((uint32_t)y2 << 16), (uint32_t)z2 | ((uint32_t)w2 << 16));
            }
            fence_async_smem();
            c_conv += clock() - cc0;
            __syncthreads();
            if (tid == 0) {
                tc_fence_after();
                const uint32_t d_tmem = tmem_base + buf * 128;
                #pragma unroll
                for (int t6 = 0; t6 < 6; ++t6) {
                    uint64_t ad = DESC_BASE | (((uint64_t)((sb + SM_A + SA[t6] * 16384) >> 4)) & 0x3FFF);
                    uint64_t bd = DESC_BASE | (((uint64_t)((sb + SM_B + buf * 49152 + SB[t6] * 16384) >> 4)) & 0x3FFF);
                    #pragma unroll
                    for (int k = 0; k < 4; ++k)
                        mma_f16_ss(d_tmem, ad + 2 * k, bd + 2 * k, IDESC,
                                   (t6 | k) ? 1u : 0u);
                }
                tc_commit(sb + SM_FULL0 + buf * 8);
            }
        }
        // ---- phase 2: epilogue of tile-1 (overlaps MMA(tile)) ----
        if (tile > 0) {
            const int t1 = tile - 1;
            const int b1 = t1 & 1;
            unsigned cw0 = clock();
            mbar_wait(sb + SM_FULL0 + b1 * 8, cf[b1]); cf[b1] ^= 1u;
            c_wait += clock() - cw0;
            tc_fence_after();
            const float4* ne4 = (const float4*)(g_ne + t1 * NTILE + h * 64);
            #pragma unroll
            for (int g = 0; g < 2; ++g) {
                uint32_t r[32];
                LDTM_X32(r, tmem_base + b1 * 128 + h * 64 + g * 32);
                tc_wait_ld();
                const int cb0 = t1 * NTILE + h * 64 + g * 32;
                #pragma unroll
                for (int q = 0; q < 8; ++q) {
                    float4 ne = ne4[g * 8 + q];
                    float d0 = fmaf(__uint_as_float(r[q*4+0]), -2.f, nx + ne.x);
                    float d1 = fmaf(__uint_as_float(r[q*4+1]), -2.f, nx + ne.y);
                    float d2 = fmaf(__uint_as_float(r[q*4+2]), -2.f, nx + ne.z);
                    float d3 = fmaf(__uint_as_float(r[q*4+3]), -2.f, nx + ne.w);
                    topk_insert(d0, cb0 + q*4 + 0, td, ti);
                    topk_insert(d1, cb0 + q*4 + 1, td, ti);
                    topk_insert(d2, cb0 + q*4 + 2, td, ti);
                    topk_insert(d3, cb0 + q*4 + 3, td, ti);
                }
            }
            tc_fence_before();
        }
    }
    if (tid == 0 && blockIdx.x == 0)
        printf("MAIN tot=%u mma_wait=%u conv=%u\n", clock() - t0, c_wait, c_conv);

    // ---- merge halves: upper warps publish their top-10, lower warps absorb ----
    __syncthreads();
    if (h == 1) {
        #pragma unroll
        for (int j = 0; j < TOPK; ++j) {
            char* p = smem + SM_MERGE + (((sp * 32 + lane) * TOPK + j) << 3);
            *(float*)p = td[j];
            *(int*)(p + 4) = ti[j];
        }
    }
    __syncthreads();
    if (h == 0) {
        #pragma unroll
        for (int j = 0; j < TOPK; ++j) {
            char* p = smem + SM_MERGE + (((sp * 32 + lane) * TOPK + j) << 3);
            topk_insert(*(float*)p, *(int*)(p + 4), td, ti);
        }

        // ---- gumbel sample over sorted top-10 (static-index select) ----
        const unsigned FULL = 0xffffffffu;
        const float* g = gum + (size_t)myrow * TOPK;
        float best = g[0] - td[0];
        int   idx  = ti[0];
        float mind = td[0];
        #pragma unroll
        for (int j = 1; j < TOPK; ++j) {
            float yj = g[j] - td[j];
            if (yj > best) { best = yj; idx = ti[j]; mind = td[j]; }
        }
        bool valid = nx > 1e-12f;
        float vm = valid ? 1.f : 0.f;
        out[IDX_OFF + myrow] = valid ? (float)idx : 0.f;
        out[MD_OFF  + myrow] = valid ? mind : 0.f;
        atomicAdd(&g_counts[idx], vm);
        unsigned bal = __ballot_sync(FULL, valid);
        if (lane == 0) atomicAdd(&g_nvalid, (float)__popc(bal));

        // ---- cooperative quantized write + vq loss ----
        float lp = 0.f;
        #pragma unroll 4
        for (int r = 0; r < 32; ++r) {
            int   ridx = __shfl_sync(FULL, idx, r);
            float rvm  = __shfl_sync(FULL, vm,  r);
            int rr = row0 + sp * 32 + r;
            float2 cv = ((const float2*)(cb  + (size_t)ridx * DIM))[lane];
            float2 xv = ((const float2*)(inp + (size_t)rr   * DIM))[lane];
            ((float2*)(out + (size_t)rr * DIM))[lane] = make_float2(cv.x * rvm, cv.y * rvm);
            float dx = cv.x - xv.x, dy = cv.y - xv.y;
            lp = fmaf(rvm * dx, dx, lp);
            lp = fmaf(rvm * dy, dy, lp);
        }
        #pragma unroll
        for (int o = 16; o > 0; o >>= 1) lp += __shfl_xor_sync(FULL, lp, o);
        if (lane == 0) atomicAdd(&g_loss, lp);
    }

    __syncthreads();
    if (w == 0) {
        asm volatile("tcgen05.relinquish_alloc_permit.cta_group::1.sync.aligned;");
        asm volatile("tcgen05.dealloc.cta_group::1.sync.aligned.b32 %0, %1;"
                     :: "r"(tmem_base), "r"(256u));
    }
#else
    if (blockIdx.x == 0 && threadIdx.x == 0) out[LOSS_OFF] = 0.f;
#endif
}

__global__ void vq_finalize(float* __restrict__ out) {
    __shared__ float red[256];
    int t = threadIdx.x;
    float nv = fmaxf(g_nvalid, 1.f);
    float h = 0.f;
    for (int i = t; i < NK; i += 256) {
        float p = g_counts[i] / nv;
        h += p * logf(p + 1e-10f);
    }
    red[t] = h; __syncthreads();
    for (int s = 128; s > 0; s >>= 1) { if (t < s) red[t] += red[t + s]; __syncthreads(); }
    if (t == 0) {
        float H = red[0];
        float perp = expf(-H);
        float ploss = -logf(perp + 1e-10f);
        float lvq = g_loss / (nv * (float)DIM);
        out[LOSS_OFF] = lvq + 0.01f * ploss;
        out[PERP_OFF] = perp;
    }
}

extern "C" void kernel_launch(void* const* d_in, const int* in_sizes, int n_in,
                              void* d_out, int out_size) {
    const float* inp = (const float*)d_in[0];
    const float* cbp = (const float*)d_in[1];
    const float* gum = (const float*)d_in[2];
    float* out = (float*)d_out;
    cudaFuncSetAttribute((const void*)vq_main,
                         cudaFuncAttributeMaxDynamicSharedMemorySize, SM_TOTAL);
    vq_prep<<<(NROWS + NK) / 8, 256>>>(inp, cbp);
    vq_main<<<NROWS / MTILE, 256, SM_TOTAL>>>(inp, cbp, gum, out);
    vq_finalize<<<1, 256>>>(out);
}